// round 13
// baseline (speedup 1.0000x reference)
#include <cuda_runtime.h>
#include <cuda_fp16.h>
#include <cstdint>

#define N_TOK 8192
#define DMODEL 1024
#define NEXP 8
#define RANK 16
#define KAUG 1152            // 1024 + 128

// ---------------------------------------------------------------------------
// Device scratch (no allocation allowed)
// ---------------------------------------------------------------------------
__device__ float  g_combine[N_TOK * NEXP];                 // [N, 8]
__device__ __half g_xaug[(size_t)N_TOK * KAUG];            // fp16 [x | hw], row-major [m][k]
__device__ __half g_Bt[(size_t)DMODEL * KAUG];             // fp16 [n][k] = [Wb row | B^T row]
__device__ __half g_At[128 * DMODEL];                      // fp16 [n=e*16+r][k]

// ---------------------------------------------------------------------------
// Helpers
// ---------------------------------------------------------------------------
__device__ __forceinline__ uint32_t smem_u32(const void* p) {
    uint32_t a;
    asm("{ .reg .u64 t; cvta.to.shared.u64 t, %1; cvt.u32.u64 %0, t; }" : "=r"(a) : "l"(p));
    return a;
}
__device__ __forceinline__ void ldsm4(uint32_t* r, uint32_t addr) {
    asm volatile("ldmatrix.sync.aligned.m8n8.x4.shared.b16 {%0,%1,%2,%3}, [%4];"
                 : "=r"(r[0]), "=r"(r[1]), "=r"(r[2]), "=r"(r[3]) : "r"(addr));
}
__device__ __forceinline__ void cp16(uint32_t dst, const void* src) {
    asm volatile("cp.async.cg.shared.global [%0], [%1], 16;" :: "r"(dst), "l"(src));
}
__device__ __forceinline__ void cp_commit() {
    asm volatile("cp.async.commit_group;" ::: "memory");
}
template <int N> __device__ __forceinline__ void cp_wait() {
    asm volatile("cp.async.wait_group %0;" :: "n"(N) : "memory");
}
__device__ __forceinline__ void mma_f16(float* c, const uint32_t* a, uint32_t b0, uint32_t b1) {
    asm volatile(
        "mma.sync.aligned.m16n8k16.row.col.f32.f16.f16.f32 "
        "{%0,%1,%2,%3}, {%4,%5,%6,%7}, {%8,%9}, {%0,%1,%2,%3};"
        : "+f"(c[0]), "+f"(c[1]), "+f"(c[2]), "+f"(c[3])
        : "r"(a[0]), "r"(a[1]), "r"(a[2]), "r"(a[3]), "r"(b0), "r"(b1));
}
// 64B rows of 4 x 16B chunks; conflict-free for STS and 8-row LDSM reads
#define SW(r, c) ((unsigned)((r) * 64 + ((((c) ^ (((r) >> 1) & 3))) << 4)))

// ---------------------------------------------------------------------------
// Prep 1: g_Bt rows, cols [0,1024) = fp16(W_base[n][k])
// ---------------------------------------------------------------------------
__global__ void build_bt_base(const float* __restrict__ Wb) {
    int n = blockIdx.x;
    int j = threadIdx.x * 4;
    float4 v = *(const float4*)(Wb + (size_t)n * DMODEL + j);
    __half2* dst = (__half2*)(g_Bt + (size_t)n * KAUG + j);
    dst[0] = __floats2half2_rn(v.x, v.y);
    dst[1] = __floats2half2_rn(v.z, v.w);
}

// Prep 2: g_Bt[n][1024+i] = fp16(B[i][n])
__global__ void build_bt_lora(const float* __restrict__ B) {
    __shared__ float tile[32][33];
    int n0 = blockIdx.x * 32, i0 = blockIdx.y * 32;
    tile[threadIdx.y][threadIdx.x] =
        B[(size_t)(i0 + threadIdx.y) * DMODEL + n0 + threadIdx.x];
    __syncthreads();
    g_Bt[(size_t)(n0 + threadIdx.y) * KAUG + DMODEL + i0 + threadIdx.x] =
        __float2half_rn(tile[threadIdx.x][threadIdx.y]);
}

// Prep 3: g_At[e*16+r][k] = fp16(A[e][k][r])
__global__ void build_at(const float* __restrict__ A) {
    __shared__ float tile[16][17];
    int e = blockIdx.y, k0 = blockIdx.x * 16;
    tile[threadIdx.x][threadIdx.y] =
        A[(size_t)e * DMODEL * RANK + (size_t)(k0 + threadIdx.y) * RANK + threadIdx.x];
    __syncthreads();
    g_At[(size_t)(e * RANK + threadIdx.y) * DMODEL + k0 + threadIdx.x] =
        __float2half_rn(tile[threadIdx.y][threadIdx.x]);
}

// ---------------------------------------------------------------------------
// Gating + fused x->fp16 conversion; Wg staged in smem; 2 tokens per warp.
// ---------------------------------------------------------------------------
__global__ __launch_bounds__(256) void gating_cvt(const float* __restrict__ x,
                                                  const float* __restrict__ Wg) {
    __shared__ float wgs[NEXP * DMODEL];   // 32 KB
#pragma unroll
    for (int i = 0; i < NEXP * DMODEL / 4 / 256; i++)
        ((float4*)wgs)[i * 256 + threadIdx.x] = ((const float4*)Wg)[i * 256 + threadIdx.x];
    __syncthreads();

    int warp = threadIdx.x >> 5, lane = threadIdx.x & 31;
    int t0 = blockIdx.x * 16 + warp * 2;
    const float* xr0 = x + (size_t)t0 * DMODEL;
    const float* xr1 = xr0 + DMODEL;
    __half* xo0 = g_xaug + (size_t)t0 * KAUG;
    __half* xo1 = xo0 + KAUG;
    float acc0[NEXP], acc1[NEXP];
#pragma unroll
    for (int e = 0; e < NEXP; e++) { acc0[e] = 0.f; acc1[e] = 0.f; }
#pragma unroll
    for (int kk = 0; kk < 8; kk++) {
        int col = kk * 128 + lane * 4;
        float4 v0 = *(const float4*)(xr0 + col);
        float4 v1 = *(const float4*)(xr1 + col);
        __half2* d0 = (__half2*)(xo0 + col);
        d0[0] = __floats2half2_rn(v0.x, v0.y);
        d0[1] = __floats2half2_rn(v0.z, v0.w);
        __half2* d1 = (__half2*)(xo1 + col);
        d1[0] = __floats2half2_rn(v1.x, v1.y);
        d1[1] = __floats2half2_rn(v1.z, v1.w);
#pragma unroll
        for (int e = 0; e < NEXP; e++) {
            float4 w = *(const float4*)(wgs + e * DMODEL + col);
            acc0[e] += v0.x * w.x + v0.y * w.y + v0.z * w.z + v0.w * w.w;
            acc1[e] += v1.x * w.x + v1.y * w.y + v1.z * w.z + v1.w * w.w;
        }
    }
#pragma unroll
    for (int e = 0; e < NEXP; e++) {
#pragma unroll
        for (int o = 16; o > 0; o >>= 1) {
            acc0[e] += __shfl_xor_sync(0xffffffffu, acc0[e], o);
            acc1[e] += __shfl_xor_sync(0xffffffffu, acc1[e], o);
        }
    }
    if (lane == 0) {
#pragma unroll
        for (int tt = 0; tt < 2; tt++) {
            float* acc = tt ? acc1 : acc0;
            int i0 = 0; float v0 = acc[0];
#pragma unroll
            for (int e = 1; e < NEXP; e++)
                if (acc[e] > v0) { v0 = acc[e]; i0 = e; }
            int i1 = -1; float v1 = -3.4e38f;
#pragma unroll
            for (int e = 0; e < NEXP; e++)
                if (e != i0 && acc[e] > v1) { v1 = acc[e]; i1 = e; }
            float e1 = expf(v1 - v0);
            float w0 = 1.f / (1.f + e1);
            float w1 = e1 * w0;
            float* c = g_combine + (t0 + tt) * NEXP;
#pragma unroll
            for (int e = 0; e < NEXP; e++) c[e] = 0.f;
            c[i0] = w0;
            c[i1] = w1;
        }
    }
}

// ---------------------------------------------------------------------------
// G1: H = x @ At^T, scaled by combine -> g_xaug cols [1024,1152)
// Block 64x64, BK=32, 3-stage, 4 warps (2Mx2N), warp tile 32x32, 128 threads.
// ---------------------------------------------------------------------------
#define G1_AB 4096                       // 64 rows * 64 B
#define G1_STAGE 8192
#define G1_SMEM (3 * G1_STAGE)           // 24576
#define G1_KT 32

__global__ __launch_bounds__(128, 4) void g1_kernel() {
    extern __shared__ char smem[];
    const uint32_t sb = smem_u32(smem);
    const int tid = threadIdx.x, lane = tid & 31, warp = tid >> 5;
    const int m0 = blockIdx.y * 64, n0 = blockIdx.x * 64;
    const int wm = (warp & 1) * 32, wn = (warp >> 1) * 32;

    const __half* ag[2]; uint32_t asw[2];
    const __half* bg[2]; uint32_t bsw[2];
#pragma unroll
    for (int i = 0; i < 2; i++) {
        int idx = i * 128 + tid, r = idx >> 2, c = idx & 3;
        ag[i] = g_xaug + (size_t)(m0 + r) * KAUG + c * 8;
        asw[i] = SW(r, c);
        bg[i] = g_At + (size_t)(n0 + r) * DMODEL + c * 8;
        bsw[i] = asw[i];
    }

    const int lr = lane & 7, mi = lane >> 3, khalf = mi >> 1, rsel = mi & 1;
    uint32_t aoff[2][2], boff[2][2];
#pragma unroll
    for (int mt = 0; mt < 2; mt++) {
        int row = wm + mt * 16 + rsel * 8 + lr;
#pragma unroll
        for (int s = 0; s < 2; s++) aoff[mt][s] = SW(row, s * 2 + khalf);
    }
#pragma unroll
    for (int nt = 0; nt < 2; nt++) {
        int row = wn + nt * 16 + rsel * 8 + lr;
#pragma unroll
        for (int s = 0; s < 2; s++) boff[nt][s] = SW(row, s * 2 + khalf);
    }

    float acc[2][4][4];
#pragma unroll
    for (int mt = 0; mt < 2; mt++)
#pragma unroll
        for (int nb = 0; nb < 4; nb++)
#pragma unroll
            for (int q = 0; q < 4; q++) acc[mt][nb][q] = 0.f;

    auto load_stage = [&](int s, int kt) {
        uint32_t base = sb + s * G1_STAGE;
#pragma unroll
        for (int i = 0; i < 2; i++) cp16(base + asw[i], ag[i] + kt * 32);
#pragma unroll
        for (int i = 0; i < 2; i++) cp16(base + G1_AB + bsw[i], bg[i] + kt * 32);
    };

    load_stage(0, 0); cp_commit();
    load_stage(1, 1); cp_commit();

    for (int kt = 0; kt < G1_KT; kt++) {
        cp_wait<1>();
        __syncthreads();
        int ld = kt + 2;
        if (ld < G1_KT) load_stage(ld % 3, ld);
        cp_commit();
        uint32_t stg = sb + (kt % 3) * G1_STAGE;
#pragma unroll
        for (int s = 0; s < 2; s++) {
            uint32_t a[2][4], b[2][4];
#pragma unroll
            for (int mt = 0; mt < 2; mt++) ldsm4(a[mt], stg + aoff[mt][s]);
#pragma unroll
            for (int nt = 0; nt < 2; nt++) ldsm4(b[nt], stg + G1_AB + boff[nt][s]);
#pragma unroll
            for (int mt = 0; mt < 2; mt++)
#pragma unroll
                for (int nb = 0; nb < 4; nb++)
                    mma_f16(acc[mt][nb], a[mt], b[nb >> 1][nb & 1], b[nb >> 1][(nb & 1) + 2]);
        }
    }
    cp_wait<0>();

    const int grp = lane >> 2, th2 = (lane & 3) * 2;
#pragma unroll
    for (int mt = 0; mt < 2; mt++) {
        int r0 = m0 + wm + mt * 16 + grp;
#pragma unroll
        for (int nb = 0; nb < 4; nb++) {
            int col = n0 + wn + nb * 8 + th2;
            int e = col >> 4;
            float w0 = g_combine[r0 * NEXP + e];
            float w1 = g_combine[(r0 + 8) * NEXP + e];
            *(__half2*)(g_xaug + (size_t)r0 * KAUG + DMODEL + col) =
                __floats2half2_rn(acc[mt][nb][0] * w0, acc[mt][nb][1] * w0);
            *(__half2*)(g_xaug + (size_t)(r0 + 8) * KAUG + DMODEL + col) =
                __floats2half2_rn(acc[mt][nb][2] * w1, acc[mt][nb][3] * w1);
        }
    }
}

// ---------------------------------------------------------------------------
// G2: out = [x|hw] @ g_Bt^T + bias
// Block 128x256, BK=32, 4-stage cp.async, 8 warps (2M x 4N), warp tile 64x64.
// 1 CTA/SM (256 regs/thread budget).
// ---------------------------------------------------------------------------
#define G2_AB 8192                       // A: 128 rows * 64 B
#define G2_BB 16384                      // B: 256 rows * 64 B
#define G2_STAGE (G2_AB + G2_BB)         // 24576
#define G2_SMEM (4 * G2_STAGE)           // 98304
#define G2_KT 36

__global__ __launch_bounds__(256, 1) void g2_kernel(const float* __restrict__ bias,
                                                    float* __restrict__ out) {
    extern __shared__ char smem[];
    const uint32_t sb = smem_u32(smem);
    const int tid = threadIdx.x, lane = tid & 31, warp = tid >> 5;
    const int m0 = blockIdx.y * 128, n0 = blockIdx.x * 256;
    const int wm = (warp & 1) * 64, wn = (warp >> 1) * 64;

    const __half* ag[2]; uint32_t asw[2];
    const __half* bg[4]; uint32_t bsw[4];
#pragma unroll
    for (int i = 0; i < 2; i++) {
        int idx = i * 256 + tid, r = idx >> 2, c = idx & 3;
        ag[i] = g_xaug + (size_t)(m0 + r) * KAUG + c * 8;
        asw[i] = SW(r, c);
    }
#pragma unroll
    for (int i = 0; i < 4; i++) {
        int idx = i * 256 + tid, r = idx >> 2, c = idx & 3;
        bg[i] = g_Bt + (size_t)(n0 + r) * KAUG + c * 8;
        bsw[i] = SW(r, c);
    }

    const int lr = lane & 7, mi = lane >> 3, khalf = mi >> 1, rsel = mi & 1;
    uint32_t aoff[4][2], boff[4][2];
#pragma unroll
    for (int mt = 0; mt < 4; mt++) {
        int row = wm + mt * 16 + rsel * 8 + lr;
#pragma unroll
        for (int s = 0; s < 2; s++) aoff[mt][s] = SW(row, s * 2 + khalf);
    }
#pragma unroll
    for (int nt = 0; nt < 4; nt++) {
        int row = wn + nt * 16 + rsel * 8 + lr;
#pragma unroll
        for (int s = 0; s < 2; s++) boff[nt][s] = SW(row, s * 2 + khalf);
    }

    float acc[4][8][4];
#pragma unroll
    for (int mt = 0; mt < 4; mt++)
#pragma unroll
        for (int nb = 0; nb < 8; nb++)
#pragma unroll
            for (int q = 0; q < 4; q++) acc[mt][nb][q] = 0.f;

    auto load_stage = [&](int s, int kt) {
        uint32_t base = sb + s * G2_STAGE;
#pragma unroll
        for (int i = 0; i < 2; i++) cp16(base + asw[i], ag[i] + kt * 32);
#pragma unroll
        for (int i = 0; i < 4; i++) cp16(base + G2_AB + bsw[i], bg[i] + kt * 32);
    };

    load_stage(0, 0); cp_commit();
    load_stage(1, 1); cp_commit();
    load_stage(2, 2); cp_commit();

    for (int kt = 0; kt < G2_KT; kt++) {
        cp_wait<2>();
        __syncthreads();
        int ld = kt + 3;
        if (ld < G2_KT) load_stage(ld & 3, ld);
        cp_commit();
        uint32_t stg = sb + (kt & 3) * G2_STAGE;
#pragma unroll
        for (int s = 0; s < 2; s++) {
            uint32_t a[4][4], b[4][4];
#pragma unroll
            for (int mt = 0; mt < 4; mt++) ldsm4(a[mt], stg + aoff[mt][s]);
#pragma unroll
            for (int nt = 0; nt < 4; nt++) ldsm4(b[nt], stg + G2_AB + boff[nt][s]);
#pragma unroll
            for (int mt = 0; mt < 4; mt++)
#pragma unroll
                for (int nb = 0; nb < 8; nb++)
                    mma_f16(acc[mt][nb], a[mt], b[nb >> 1][nb & 1], b[nb >> 1][(nb & 1) + 2]);
        }
    }
    cp_wait<0>();

    const int grp = lane >> 2, th2 = (lane & 3) * 2;
#pragma unroll
    for (int mt = 0; mt < 4; mt++) {
        int r0 = m0 + wm + mt * 16 + grp;
#pragma unroll
        for (int nb = 0; nb < 8; nb++) {
            int col = n0 + wn + nb * 8 + th2;
            float2 bv = *(const float2*)(bias + col);
            float2 o0 = make_float2(acc[mt][nb][0] + bv.x, acc[mt][nb][1] + bv.y);
            float2 o1 = make_float2(acc[mt][nb][2] + bv.x, acc[mt][nb][3] + bv.y);
            *(float2*)(out + (size_t)r0 * DMODEL + col) = o0;
            *(float2*)(out + (size_t)(r0 + 8) * DMODEL + col) = o1;
        }
    }
}

// ---------------------------------------------------------------------------
extern "C" void kernel_launch(void* const* d_in, const int* in_sizes, int n_in,
                              void* d_out, int out_size) {
    const float* x  = (const float*)d_in[0];
    const float* Wg = (const float*)d_in[1];
    const float* A  = (const float*)d_in[2];
    const float* B  = (const float*)d_in[3];
    const float* Wb = (const float*)d_in[4];
    const float* bb = (const float*)d_in[5];
    float* out = (float*)d_out;

    static int attr_done = 0;
    if (!attr_done) {
        cudaFuncSetAttribute(g1_kernel, cudaFuncAttributeMaxDynamicSharedMemorySize, G1_SMEM);
        cudaFuncSetAttribute(g2_kernel, cudaFuncAttributeMaxDynamicSharedMemorySize, G2_SMEM);
        attr_done = 1;
    }

    build_bt_base<<<DMODEL, 256>>>(Wb);
    build_bt_lora<<<dim3(32, 4), dim3(32, 32)>>>(B);
    build_at<<<dim3(64, 8), dim3(16, 16)>>>(A);
    gating_cvt<<<N_TOK / 16, 256>>>(x, Wg);
    g1_kernel<<<dim3(2, N_TOK / 64), 128, G1_SMEM>>>();
    g2_kernel<<<dim3(DMODEL / 256, N_TOK / 128), 256, G2_SMEM>>>(bb, out);
}

// round 14
// speedup vs baseline: 1.0579x; 1.0579x over previous
#include <cuda_runtime.h>
#include <cuda_fp16.h>
#include <cstdint>

#define N_TOK 8192
#define DMODEL 1024
#define NEXP 8
#define RANK 16
#define KAUG 1152            // 1024 + 128

// ---------------------------------------------------------------------------
// Device scratch (no allocation allowed)
// ---------------------------------------------------------------------------
__device__ float  g_combine[N_TOK * NEXP];                 // [N, 8]
__device__ __half g_xaug[(size_t)N_TOK * KAUG];            // fp16 [x | hw], row-major [m][k]
__device__ __half g_Bt[(size_t)DMODEL * KAUG];             // fp16 [n][k] = [Wb row | B^T row]
__device__ __half g_At[128 * DMODEL];                      // fp16 [n=e*16+r][k]

// ---------------------------------------------------------------------------
// Helpers
// ---------------------------------------------------------------------------
__device__ __forceinline__ uint32_t smem_u32(const void* p) {
    uint32_t a;
    asm("{ .reg .u64 t; cvta.to.shared.u64 t, %1; cvt.u32.u64 %0, t; }" : "=r"(a) : "l"(p));
    return a;
}
__device__ __forceinline__ void ldsm4(uint32_t* r, uint32_t addr) {
    asm volatile("ldmatrix.sync.aligned.m8n8.x4.shared.b16 {%0,%1,%2,%3}, [%4];"
                 : "=r"(r[0]), "=r"(r[1]), "=r"(r[2]), "=r"(r[3]) : "r"(addr));
}
__device__ __forceinline__ void cp16(uint32_t dst, const void* src) {
    asm volatile("cp.async.cg.shared.global [%0], [%1], 16;" :: "r"(dst), "l"(src));
}
__device__ __forceinline__ void cp_commit() {
    asm volatile("cp.async.commit_group;" ::: "memory");
}
template <int N> __device__ __forceinline__ void cp_wait() {
    asm volatile("cp.async.wait_group %0;" :: "n"(N) : "memory");
}
__device__ __forceinline__ void mma_f16(float* c, const uint32_t* a, uint32_t b0, uint32_t b1) {
    asm volatile(
        "mma.sync.aligned.m16n8k16.row.col.f32.f16.f16.f32 "
        "{%0,%1,%2,%3}, {%4,%5,%6,%7}, {%8,%9}, {%0,%1,%2,%3};"
        : "+f"(c[0]), "+f"(c[1]), "+f"(c[2]), "+f"(c[3])
        : "r"(a[0]), "r"(a[1]), "r"(a[2]), "r"(a[3]), "r"(b0), "r"(b1));
}
// 64B rows of 4 x 16B chunks; conflict-free for STS and 8-row LDSM reads
#define SW(r, c) ((unsigned)((r) * 64 + ((((c) ^ (((r) >> 1) & 3))) << 4)))

// ---------------------------------------------------------------------------
// Merged prep kernel: flat grid, 256 threads.
//   blocks [0, 1024):        g_Bt cols [0,1024) = fp16(W_base[n][k])
//   blocks [1024, 1152):     g_Bt[n][1024+i] = fp16(B[i][n])   (32x32 tiles)
//   blocks [1152, 1664):     g_At[e*16+r][k] = fp16(A[e][k][r]) (16-k tiles)
// ---------------------------------------------------------------------------
__global__ __launch_bounds__(256) void prep_all(const float* __restrict__ Wb,
                                                const float* __restrict__ B,
                                                const float* __restrict__ A) {
    int b = blockIdx.x;
    int tid = threadIdx.x;
    if (b < 1024) {
        int n = b;
        int j = tid * 4;
        float4 v = *(const float4*)(Wb + (size_t)n * DMODEL + j);
        __half2* dst = (__half2*)(g_Bt + (size_t)n * KAUG + j);
        dst[0] = __floats2half2_rn(v.x, v.y);
        dst[1] = __floats2half2_rn(v.z, v.w);
    } else if (b < 1152) {
        __shared__ float tile[32][33];
        int t = b - 1024;
        int n0 = (t & 31) * 32, i0 = (t >> 5) * 32;
        int tx = tid & 31, tg = tid >> 5;
#pragma unroll
        for (int p = 0; p < 4; p++) {
            int iy = tg + p * 8;
            tile[iy][tx] = B[(size_t)(i0 + iy) * DMODEL + n0 + tx];
        }
        __syncthreads();
#pragma unroll
        for (int p = 0; p < 4; p++) {
            int ny = tg + p * 8;
            g_Bt[(size_t)(n0 + ny) * KAUG + DMODEL + i0 + tx] =
                __float2half_rn(tile[tx][ny]);
        }
    } else {
        __shared__ float tile[16][17];
        int t = b - 1152;
        int e = t >> 6, k0 = (t & 63) * 16;
        int tx = tid & 15, ty = tid >> 4;
        tile[tx][ty] = A[(size_t)e * DMODEL * RANK + (size_t)(k0 + ty) * RANK + tx];
        __syncthreads();
        g_At[(size_t)(e * RANK + ty) * DMODEL + k0 + tx] =
            __float2half_rn(tile[ty][tx]);
    }
}

// ---------------------------------------------------------------------------
// Gating + fused x->fp16 conversion; Wg staged in smem; 4 tokens per warp.
// ---------------------------------------------------------------------------
__global__ __launch_bounds__(256) void gating_cvt(const float* __restrict__ x,
                                                  const float* __restrict__ Wg) {
    __shared__ float wgs[NEXP * DMODEL];   // 32 KB
#pragma unroll
    for (int i = 0; i < NEXP * DMODEL / 4 / 256; i++)
        ((float4*)wgs)[i * 256 + threadIdx.x] = ((const float4*)Wg)[i * 256 + threadIdx.x];
    __syncthreads();

    int warp = threadIdx.x >> 5, lane = threadIdx.x & 31;
    int t0 = blockIdx.x * 32 + warp * 4;
    const float* xr = x + (size_t)t0 * DMODEL;
    __half* xo = g_xaug + (size_t)t0 * KAUG;
    float acc[4][NEXP];
#pragma unroll
    for (int tt = 0; tt < 4; tt++)
#pragma unroll
        for (int e = 0; e < NEXP; e++) acc[tt][e] = 0.f;

#pragma unroll
    for (int kk = 0; kk < 8; kk++) {
        int col = kk * 128 + lane * 4;
        float4 v[4];
#pragma unroll
        for (int tt = 0; tt < 4; tt++) {
            v[tt] = *(const float4*)(xr + (size_t)tt * DMODEL + col);
            __half2* d = (__half2*)(xo + (size_t)tt * KAUG + col);
            d[0] = __floats2half2_rn(v[tt].x, v[tt].y);
            d[1] = __floats2half2_rn(v[tt].z, v[tt].w);
        }
#pragma unroll
        for (int e = 0; e < NEXP; e++) {
            float4 w = *(const float4*)(wgs + e * DMODEL + col);
#pragma unroll
            for (int tt = 0; tt < 4; tt++)
                acc[tt][e] += v[tt].x * w.x + v[tt].y * w.y + v[tt].z * w.z + v[tt].w * w.w;
        }
    }
#pragma unroll
    for (int tt = 0; tt < 4; tt++)
#pragma unroll
        for (int e = 0; e < NEXP; e++) {
#pragma unroll
            for (int o = 16; o > 0; o >>= 1)
                acc[tt][e] += __shfl_xor_sync(0xffffffffu, acc[tt][e], o);
        }
    if (lane == 0) {
#pragma unroll
        for (int tt = 0; tt < 4; tt++) {
            float* a = acc[tt];
            int i0 = 0; float v0 = a[0];
#pragma unroll
            for (int e = 1; e < NEXP; e++)
                if (a[e] > v0) { v0 = a[e]; i0 = e; }
            int i1 = -1; float v1 = -3.4e38f;
#pragma unroll
            for (int e = 0; e < NEXP; e++)
                if (e != i0 && a[e] > v1) { v1 = a[e]; i1 = e; }
            float e1 = expf(v1 - v0);
            float w0 = 1.f / (1.f + e1);
            float w1 = e1 * w0;
            float* c = g_combine + (t0 + tt) * NEXP;
#pragma unroll
            for (int e = 0; e < NEXP; e++) c[e] = 0.f;
            c[i0] = w0;
            c[i1] = w1;
        }
    }
}

// ---------------------------------------------------------------------------
// G1: H = x @ At^T, scaled by combine -> g_xaug cols [1024,1152)
// Block 64x64, BK=32, 3-stage, 4 warps (2Mx2N), warp tile 32x32, 128 threads.
// ---------------------------------------------------------------------------
#define G1_AB 4096                       // 64 rows * 64 B
#define G1_STAGE 8192
#define G1_SMEM (3 * G1_STAGE)           // 24576
#define G1_KT 32

__global__ __launch_bounds__(128, 4) void g1_kernel() {
    extern __shared__ char smem[];
    const uint32_t sb = smem_u32(smem);
    const int tid = threadIdx.x, lane = tid & 31, warp = tid >> 5;
    const int m0 = blockIdx.y * 64, n0 = blockIdx.x * 64;
    const int wm = (warp & 1) * 32, wn = (warp >> 1) * 32;

    const __half* ag[2]; uint32_t asw[2];
    const __half* bg[2]; uint32_t bsw[2];
#pragma unroll
    for (int i = 0; i < 2; i++) {
        int idx = i * 128 + tid, r = idx >> 2, c = idx & 3;
        ag[i] = g_xaug + (size_t)(m0 + r) * KAUG + c * 8;
        asw[i] = SW(r, c);
        bg[i] = g_At + (size_t)(n0 + r) * DMODEL + c * 8;
        bsw[i] = asw[i];
    }

    const int lr = lane & 7, mi = lane >> 3, khalf = mi >> 1, rsel = mi & 1;
    uint32_t aoff[2][2], boff[2][2];
#pragma unroll
    for (int mt = 0; mt < 2; mt++) {
        int row = wm + mt * 16 + rsel * 8 + lr;
#pragma unroll
        for (int s = 0; s < 2; s++) aoff[mt][s] = SW(row, s * 2 + khalf);
    }
#pragma unroll
    for (int nt = 0; nt < 2; nt++) {
        int row = wn + nt * 16 + rsel * 8 + lr;
#pragma unroll
        for (int s = 0; s < 2; s++) boff[nt][s] = SW(row, s * 2 + khalf);
    }

    float acc[2][4][4];
#pragma unroll
    for (int mt = 0; mt < 2; mt++)
#pragma unroll
        for (int nb = 0; nb < 4; nb++)
#pragma unroll
            for (int q = 0; q < 4; q++) acc[mt][nb][q] = 0.f;

    auto load_stage = [&](int s, int kt) {
        uint32_t base = sb + s * G1_STAGE;
#pragma unroll
        for (int i = 0; i < 2; i++) cp16(base + asw[i], ag[i] + kt * 32);
#pragma unroll
        for (int i = 0; i < 2; i++) cp16(base + G1_AB + bsw[i], bg[i] + kt * 32);
    };

    load_stage(0, 0); cp_commit();
    load_stage(1, 1); cp_commit();

    for (int kt = 0; kt < G1_KT; kt++) {
        cp_wait<1>();
        __syncthreads();
        int ld = kt + 2;
        if (ld < G1_KT) load_stage(ld % 3, ld);
        cp_commit();
        uint32_t stg = sb + (kt % 3) * G1_STAGE;
#pragma unroll
        for (int s = 0; s < 2; s++) {
            uint32_t a[2][4], b[2][4];
#pragma unroll
            for (int mt = 0; mt < 2; mt++) ldsm4(a[mt], stg + aoff[mt][s]);
#pragma unroll
            for (int nt = 0; nt < 2; nt++) ldsm4(b[nt], stg + G1_AB + boff[nt][s]);
#pragma unroll
            for (int mt = 0; mt < 2; mt++)
#pragma unroll
                for (int nb = 0; nb < 4; nb++)
                    mma_f16(acc[mt][nb], a[mt], b[nb >> 1][nb & 1], b[nb >> 1][(nb & 1) + 2]);
        }
    }
    cp_wait<0>();

    const int grp = lane >> 2, th2 = (lane & 3) * 2;
#pragma unroll
    for (int mt = 0; mt < 2; mt++) {
        int r0 = m0 + wm + mt * 16 + grp;
#pragma unroll
        for (int nb = 0; nb < 4; nb++) {
            int col = n0 + wn + nb * 8 + th2;
            int e = col >> 4;
            float w0 = g_combine[r0 * NEXP + e];
            float w1 = g_combine[(r0 + 8) * NEXP + e];
            *(__half2*)(g_xaug + (size_t)r0 * KAUG + DMODEL + col) =
                __floats2half2_rn(acc[mt][nb][0] * w0, acc[mt][nb][1] * w0);
            *(__half2*)(g_xaug + (size_t)(r0 + 8) * KAUG + DMODEL + col) =
                __floats2half2_rn(acc[mt][nb][2] * w1, acc[mt][nb][3] * w1);
        }
    }
}

// ---------------------------------------------------------------------------
// G2: out = [x|hw] @ g_Bt^T + bias   (R11 proven config)
// Block 128x128, BK=32, 4-stage cp.async, 8 warps (2M x 4N), warp tile 64x32.
// ---------------------------------------------------------------------------
#define GM_AB 8192                       // 128 rows * 64 B
#define GM_STAGE 16384
#define G2_SMEM (4 * GM_STAGE)           // 65536
#define G2_KT 36

__global__ __launch_bounds__(256, 2) void g2_kernel(const float* __restrict__ bias,
                                                    float* __restrict__ out) {
    extern __shared__ char smem[];
    const uint32_t sb = smem_u32(smem);
    const int tid = threadIdx.x, lane = tid & 31, warp = tid >> 5;
    const int m0 = blockIdx.y * 128, n0 = blockIdx.x * 128;
    const int wm = (warp & 1) * 64, wn = (warp >> 1) * 32;

    const __half* ag[2]; uint32_t asw[2];
    const __half* bg[2]; uint32_t bsw[2];
#pragma unroll
    for (int i = 0; i < 2; i++) {
        int idx = i * 256 + tid, r = idx >> 2, c = idx & 3;
        ag[i] = g_xaug + (size_t)(m0 + r) * KAUG + c * 8;
        asw[i] = SW(r, c);
        bg[i] = g_Bt + (size_t)(n0 + r) * KAUG + c * 8;
        bsw[i] = asw[i];
    }

    const int lr = lane & 7, mi = lane >> 3, khalf = mi >> 1, rsel = mi & 1;
    uint32_t aoff[4][2], boff[2][2];
#pragma unroll
    for (int mt = 0; mt < 4; mt++) {
        int row = wm + mt * 16 + rsel * 8 + lr;
#pragma unroll
        for (int s = 0; s < 2; s++) aoff[mt][s] = SW(row, s * 2 + khalf);
    }
#pragma unroll
    for (int nt = 0; nt < 2; nt++) {
        int row = wn + nt * 16 + rsel * 8 + lr;
#pragma unroll
        for (int s = 0; s < 2; s++) boff[nt][s] = SW(row, s * 2 + khalf);
    }

    float acc[4][4][4];
#pragma unroll
    for (int mt = 0; mt < 4; mt++)
#pragma unroll
        for (int nb = 0; nb < 4; nb++)
#pragma unroll
            for (int q = 0; q < 4; q++) acc[mt][nb][q] = 0.f;

    auto load_stage = [&](int s, int kt) {
        uint32_t base = sb + s * GM_STAGE;
#pragma unroll
        for (int i = 0; i < 2; i++) cp16(base + asw[i], ag[i] + kt * 32);
#pragma unroll
        for (int i = 0; i < 2; i++) cp16(base + GM_AB + bsw[i], bg[i] + kt * 32);
    };

    load_stage(0, 0); cp_commit();
    load_stage(1, 1); cp_commit();
    load_stage(2, 2); cp_commit();

    for (int kt = 0; kt < G2_KT; kt++) {
        cp_wait<2>();
        __syncthreads();
        int ld = kt + 3;
        if (ld < G2_KT) load_stage(ld & 3, ld);
        cp_commit();
        uint32_t stg = sb + (kt & 3) * GM_STAGE;
#pragma unroll
        for (int s = 0; s < 2; s++) {
            uint32_t a[4][4], b[2][4];
#pragma unroll
            for (int mt = 0; mt < 4; mt++) ldsm4(a[mt], stg + aoff[mt][s]);
#pragma unroll
            for (int nt = 0; nt < 2; nt++) ldsm4(b[nt], stg + GM_AB + boff[nt][s]);
#pragma unroll
            for (int mt = 0; mt < 4; mt++)
#pragma unroll
                for (int nb = 0; nb < 4; nb++)
                    mma_f16(acc[mt][nb], a[mt], b[nb >> 1][nb & 1], b[nb >> 1][(nb & 1) + 2]);
        }
    }
    cp_wait<0>();

    const int grp = lane >> 2, th2 = (lane & 3) * 2;
#pragma unroll
    for (int mt = 0; mt < 4; mt++) {
        int r0 = m0 + wm + mt * 16 + grp;
#pragma unroll
        for (int nb = 0; nb < 4; nb++) {
            int col = n0 + wn + nb * 8 + th2;
            float2 bv = *(const float2*)(bias + col);
            float2 o0 = make_float2(acc[mt][nb][0] + bv.x, acc[mt][nb][1] + bv.y);
            float2 o1 = make_float2(acc[mt][nb][2] + bv.x, acc[mt][nb][3] + bv.y);
            *(float2*)(out + (size_t)r0 * DMODEL + col) = o0;
            *(float2*)(out + (size_t)(r0 + 8) * DMODEL + col) = o1;
        }
    }
}

// ---------------------------------------------------------------------------
extern "C" void kernel_launch(void* const* d_in, const int* in_sizes, int n_in,
                              void* d_out, int out_size) {
    const float* x  = (const float*)d_in[0];
    const float* Wg = (const float*)d_in[1];
    const float* A  = (const float*)d_in[2];
    const float* B  = (const float*)d_in[3];
    const float* Wb = (const float*)d_in[4];
    const float* bb = (const float*)d_in[5];
    float* out = (float*)d_out;

    static int attr_done = 0;
    if (!attr_done) {
        cudaFuncSetAttribute(g1_kernel, cudaFuncAttributeMaxDynamicSharedMemorySize, G1_SMEM);
        cudaFuncSetAttribute(g2_kernel, cudaFuncAttributeMaxDynamicSharedMemorySize, G2_SMEM);
        attr_done = 1;
    }

    prep_all<<<1664, 256>>>(Wb, B, A);
    gating_cvt<<<N_TOK / 32, 256>>>(x, Wg);
    g1_kernel<<<dim3(2, N_TOK / 64), 128, G1_SMEM>>>();
    g2_kernel<<<dim3(DMODEL / 128, N_TOK / 128), 256, G2_SMEM>>>(bb, out);
}

// round 15
// speedup vs baseline: 1.0902x; 1.0305x over previous
#include <cuda_runtime.h>
#include <cuda_fp16.h>
#include <cstdint>

#define N_TOK 8192
#define DMODEL 1024
#define NEXP 8
#define RANK 16
#define KAUG 1152            // 1024 + 128

// ---------------------------------------------------------------------------
// Device scratch (no allocation allowed)
// ---------------------------------------------------------------------------
__device__ float  g_combine[N_TOK * NEXP];                 // [N, 8]
__device__ __half g_xaug[(size_t)N_TOK * KAUG];            // fp16 [x | hw], row-major [m][k]
__device__ __half g_Bt[(size_t)DMODEL * KAUG];             // fp16 [n][k] = [Wb row | B^T row]
__device__ __half g_At[128 * DMODEL];                      // fp16 [n=e*16+r][k]

// ---------------------------------------------------------------------------
// Helpers
// ---------------------------------------------------------------------------
__device__ __forceinline__ uint32_t smem_u32(const void* p) {
    uint32_t a;
    asm("{ .reg .u64 t; cvta.to.shared.u64 t, %1; cvt.u32.u64 %0, t; }" : "=r"(a) : "l"(p));
    return a;
}
__device__ __forceinline__ void ldsm4(uint32_t* r, uint32_t addr) {
    asm volatile("ldmatrix.sync.aligned.m8n8.x4.shared.b16 {%0,%1,%2,%3}, [%4];"
                 : "=r"(r[0]), "=r"(r[1]), "=r"(r[2]), "=r"(r[3]) : "r"(addr));
}
__device__ __forceinline__ void cp16(uint32_t dst, const void* src) {
    asm volatile("cp.async.cg.shared.global [%0], [%1], 16;" :: "r"(dst), "l"(src));
}
__device__ __forceinline__ void cp_commit() {
    asm volatile("cp.async.commit_group;" ::: "memory");
}
template <int N> __device__ __forceinline__ void cp_wait() {
    asm volatile("cp.async.wait_group %0;" :: "n"(N) : "memory");
}
__device__ __forceinline__ void mma_f16(float* c, const uint32_t* a, uint32_t b0, uint32_t b1) {
    asm volatile(
        "mma.sync.aligned.m16n8k16.row.col.f32.f16.f16.f32 "
        "{%0,%1,%2,%3}, {%4,%5,%6,%7}, {%8,%9}, {%0,%1,%2,%3};"
        : "+f"(c[0]), "+f"(c[1]), "+f"(c[2]), "+f"(c[3])
        : "r"(a[0]), "r"(a[1]), "r"(a[2]), "r"(a[3]), "r"(b0), "r"(b1));
}
// 64B rows of 4 x 16B chunks (g1 tiles)
#define SW(r, c) ((unsigned)((r) * 64 + ((((c) ^ (((r) >> 1) & 3))) << 4)))
// 128B rows of 8 x 16B chunks (g2 tiles)
#define SW8(r, c) ((unsigned)((r) * 128 + ((((c) ^ ((r) & 7))) << 4)))

// ---------------------------------------------------------------------------
// Merged prep kernel: flat grid, 256 threads.
// ---------------------------------------------------------------------------
__global__ __launch_bounds__(256) void prep_all(const float* __restrict__ Wb,
                                                const float* __restrict__ B,
                                                const float* __restrict__ A) {
    int b = blockIdx.x;
    int tid = threadIdx.x;
    if (b < 1024) {
        int n = b;
        int j = tid * 4;
        float4 v = *(const float4*)(Wb + (size_t)n * DMODEL + j);
        __half2* dst = (__half2*)(g_Bt + (size_t)n * KAUG + j);
        dst[0] = __floats2half2_rn(v.x, v.y);
        dst[1] = __floats2half2_rn(v.z, v.w);
    } else if (b < 1152) {
        __shared__ float tile[32][33];
        int t = b - 1024;
        int n0 = (t & 31) * 32, i0 = (t >> 5) * 32;
        int tx = tid & 31, tg = tid >> 5;
#pragma unroll
        for (int p = 0; p < 4; p++) {
            int iy = tg + p * 8;
            tile[iy][tx] = B[(size_t)(i0 + iy) * DMODEL + n0 + tx];
        }
        __syncthreads();
#pragma unroll
        for (int p = 0; p < 4; p++) {
            int ny = tg + p * 8;
            g_Bt[(size_t)(n0 + ny) * KAUG + DMODEL + i0 + tx] =
                __float2half_rn(tile[tx][ny]);
        }
    } else {
        __shared__ float tile[16][17];
        int t = b - 1152;
        int e = t >> 6, k0 = (t & 63) * 16;
        int tx = tid & 15, ty = tid >> 4;
        tile[tx][ty] = A[(size_t)e * DMODEL * RANK + (size_t)(k0 + ty) * RANK + tx];
        __syncthreads();
        g_At[(size_t)(e * RANK + ty) * DMODEL + k0 + tx] =
            __float2half_rn(tile[ty][tx]);
    }
}

// ---------------------------------------------------------------------------
// Gating + fused x->fp16 conversion; Wg staged in smem; 4 tokens per warp.
// ---------------------------------------------------------------------------
__global__ __launch_bounds__(256) void gating_cvt(const float* __restrict__ x,
                                                  const float* __restrict__ Wg) {
    __shared__ float wgs[NEXP * DMODEL];   // 32 KB
#pragma unroll
    for (int i = 0; i < NEXP * DMODEL / 4 / 256; i++)
        ((float4*)wgs)[i * 256 + threadIdx.x] = ((const float4*)Wg)[i * 256 + threadIdx.x];
    __syncthreads();

    int warp = threadIdx.x >> 5, lane = threadIdx.x & 31;
    int t0 = blockIdx.x * 32 + warp * 4;
    const float* xr = x + (size_t)t0 * DMODEL;
    __half* xo = g_xaug + (size_t)t0 * KAUG;
    float acc[4][NEXP];
#pragma unroll
    for (int tt = 0; tt < 4; tt++)
#pragma unroll
        for (int e = 0; e < NEXP; e++) acc[tt][e] = 0.f;

#pragma unroll
    for (int kk = 0; kk < 8; kk++) {
        int col = kk * 128 + lane * 4;
        float4 v[4];
#pragma unroll
        for (int tt = 0; tt < 4; tt++) {
            v[tt] = *(const float4*)(xr + (size_t)tt * DMODEL + col);
            __half2* d = (__half2*)(xo + (size_t)tt * KAUG + col);
            d[0] = __floats2half2_rn(v[tt].x, v[tt].y);
            d[1] = __floats2half2_rn(v[tt].z, v[tt].w);
        }
#pragma unroll
        for (int e = 0; e < NEXP; e++) {
            float4 w = *(const float4*)(wgs + e * DMODEL + col);
#pragma unroll
            for (int tt = 0; tt < 4; tt++)
                acc[tt][e] += v[tt].x * w.x + v[tt].y * w.y + v[tt].z * w.z + v[tt].w * w.w;
        }
    }
#pragma unroll
    for (int tt = 0; tt < 4; tt++)
#pragma unroll
        for (int e = 0; e < NEXP; e++) {
#pragma unroll
            for (int o = 16; o > 0; o >>= 1)
                acc[tt][e] += __shfl_xor_sync(0xffffffffu, acc[tt][e], o);
        }
    if (lane == 0) {
#pragma unroll
        for (int tt = 0; tt < 4; tt++) {
            float* a = acc[tt];
            int i0 = 0; float v0 = a[0];
#pragma unroll
            for (int e = 1; e < NEXP; e++)
                if (a[e] > v0) { v0 = a[e]; i0 = e; }
            int i1 = -1; float v1 = -3.4e38f;
#pragma unroll
            for (int e = 0; e < NEXP; e++)
                if (e != i0 && a[e] > v1) { v1 = a[e]; i1 = e; }
            float e1 = expf(v1 - v0);
            float w0 = 1.f / (1.f + e1);
            float w1 = e1 * w0;
            float* c = g_combine + (t0 + tt) * NEXP;
#pragma unroll
            for (int e = 0; e < NEXP; e++) c[e] = 0.f;
            c[i0] = w0;
            c[i1] = w1;
        }
    }
}

// ---------------------------------------------------------------------------
// G1: H = x @ At^T, scaled by combine -> g_xaug cols [1024,1152)
// Block 64x64, BK=32, 3-stage, 4 warps (2Mx2N), warp tile 32x32, 128 threads.
// ---------------------------------------------------------------------------
#define G1_AB 4096                       // 64 rows * 64 B
#define G1_STAGE 8192
#define G1_SMEM (3 * G1_STAGE)           // 24576
#define G1_KT 32

__global__ __launch_bounds__(128, 4) void g1_kernel() {
    extern __shared__ char smem[];
    const uint32_t sb = smem_u32(smem);
    const int tid = threadIdx.x, lane = tid & 31, warp = tid >> 5;
    const int m0 = blockIdx.y * 64, n0 = blockIdx.x * 64;
    const int wm = (warp & 1) * 32, wn = (warp >> 1) * 32;

    const __half* ag[2]; uint32_t asw[2];
    const __half* bg[2]; uint32_t bsw[2];
#pragma unroll
    for (int i = 0; i < 2; i++) {
        int idx = i * 128 + tid, r = idx >> 2, c = idx & 3;
        ag[i] = g_xaug + (size_t)(m0 + r) * KAUG + c * 8;
        asw[i] = SW(r, c);
        bg[i] = g_At + (size_t)(n0 + r) * DMODEL + c * 8;
        bsw[i] = asw[i];
    }

    const int lr = lane & 7, mi = lane >> 3, khalf = mi >> 1, rsel = mi & 1;
    uint32_t aoff[2][2], boff[2][2];
#pragma unroll
    for (int mt = 0; mt < 2; mt++) {
        int row = wm + mt * 16 + rsel * 8 + lr;
#pragma unroll
        for (int s = 0; s < 2; s++) aoff[mt][s] = SW(row, s * 2 + khalf);
    }
#pragma unroll
    for (int nt = 0; nt < 2; nt++) {
        int row = wn + nt * 16 + rsel * 8 + lr;
#pragma unroll
        for (int s = 0; s < 2; s++) boff[nt][s] = SW(row, s * 2 + khalf);
    }

    float acc[2][4][4];
#pragma unroll
    for (int mt = 0; mt < 2; mt++)
#pragma unroll
        for (int nb = 0; nb < 4; nb++)
#pragma unroll
            for (int q = 0; q < 4; q++) acc[mt][nb][q] = 0.f;

    auto load_stage = [&](int s, int kt) {
        uint32_t base = sb + s * G1_STAGE;
#pragma unroll
        for (int i = 0; i < 2; i++) cp16(base + asw[i], ag[i] + kt * 32);
#pragma unroll
        for (int i = 0; i < 2; i++) cp16(base + G1_AB + bsw[i], bg[i] + kt * 32);
    };

    load_stage(0, 0); cp_commit();
    load_stage(1, 1); cp_commit();

    for (int kt = 0; kt < G1_KT; kt++) {
        cp_wait<1>();
        __syncthreads();
        int ld = kt + 2;
        if (ld < G1_KT) load_stage(ld % 3, ld);
        cp_commit();
        uint32_t stg = sb + (kt % 3) * G1_STAGE;
#pragma unroll
        for (int s = 0; s < 2; s++) {
            uint32_t a[2][4], b[2][4];
#pragma unroll
            for (int mt = 0; mt < 2; mt++) ldsm4(a[mt], stg + aoff[mt][s]);
#pragma unroll
            for (int nt = 0; nt < 2; nt++) ldsm4(b[nt], stg + G1_AB + boff[nt][s]);
#pragma unroll
            for (int mt = 0; mt < 2; mt++)
#pragma unroll
                for (int nb = 0; nb < 4; nb++)
                    mma_f16(acc[mt][nb], a[mt], b[nb >> 1][nb & 1], b[nb >> 1][(nb & 1) + 2]);
        }
    }
    cp_wait<0>();

    const int grp = lane >> 2, th2 = (lane & 3) * 2;
#pragma unroll
    for (int mt = 0; mt < 2; mt++) {
        int r0 = m0 + wm + mt * 16 + grp;
#pragma unroll
        for (int nb = 0; nb < 4; nb++) {
            int col = n0 + wn + nb * 8 + th2;
            int e = col >> 4;
            float w0 = g_combine[r0 * NEXP + e];
            float w1 = g_combine[(r0 + 8) * NEXP + e];
            *(__half2*)(g_xaug + (size_t)r0 * KAUG + DMODEL + col) =
                __floats2half2_rn(acc[mt][nb][0] * w0, acc[mt][nb][1] * w0);
            *(__half2*)(g_xaug + (size_t)(r0 + 8) * KAUG + DMODEL + col) =
                __floats2half2_rn(acc[mt][nb][2] * w1, acc[mt][nb][3] * w1);
        }
    }
}

// ---------------------------------------------------------------------------
// G2: out = [x|hw] @ g_Bt^T + bias
// Block 128x128, BK=64, 3-stage cp.async, 8 warps (2M x 4N), warp tile 64x32.
// 4 independent k-steps per barrier for ldsm/mma overlap.
// ---------------------------------------------------------------------------
#define G2_AB 16384                      // 128 rows * 128 B
#define G2_STAGE 32768                   // (128+128) rows * 128 B
#define G2_SMEM (3 * G2_STAGE)           // 98304
#define G2_KT 18

__global__ __launch_bounds__(256, 2) void g2_kernel(const float* __restrict__ bias,
                                                    float* __restrict__ out) {
    extern __shared__ char smem[];
    const uint32_t sb = smem_u32(smem);
    const int tid = threadIdx.x, lane = tid & 31, warp = tid >> 5;
    const int m0 = blockIdx.y * 128, n0 = blockIdx.x * 128;
    const int wm = (warp & 1) * 64, wn = (warp >> 1) * 32;

    const __half* ag[4]; uint32_t asw[4];
    const __half* bg[4]; uint32_t bsw[4];
#pragma unroll
    for (int i = 0; i < 4; i++) {
        int idx = i * 256 + tid, r = idx >> 3, c = idx & 7;
        ag[i] = g_xaug + (size_t)(m0 + r) * KAUG + c * 8;
        asw[i] = SW8(r, c);
        bg[i] = g_Bt + (size_t)(n0 + r) * KAUG + c * 8;
        bsw[i] = asw[i];
    }

    const int lr = lane & 7, mi = lane >> 3, khalf = mi >> 1, rsel = mi & 1;
    uint32_t abase[4], axor[4], bbase[2], bxor[2];
#pragma unroll
    for (int mt = 0; mt < 4; mt++) {
        int row = wm + mt * 16 + rsel * 8 + lr;
        abase[mt] = row * 128;
        axor[mt] = row & 7;
    }
#pragma unroll
    for (int nt = 0; nt < 2; nt++) {
        int row = wn + nt * 16 + rsel * 8 + lr;
        bbase[nt] = row * 128;
        bxor[nt] = row & 7;
    }

    float acc[4][4][4];
#pragma unroll
    for (int mt = 0; mt < 4; mt++)
#pragma unroll
        for (int nb = 0; nb < 4; nb++)
#pragma unroll
            for (int q = 0; q < 4; q++) acc[mt][nb][q] = 0.f;

    auto load_stage = [&](int s, int kt) {
        uint32_t base = sb + s * G2_STAGE;
#pragma unroll
        for (int i = 0; i < 4; i++) cp16(base + asw[i], ag[i] + kt * 64);
#pragma unroll
        for (int i = 0; i < 4; i++) cp16(base + G2_AB + bsw[i], bg[i] + kt * 64);
    };

    load_stage(0, 0); cp_commit();
    load_stage(1, 1); cp_commit();

    for (int kt = 0; kt < G2_KT; kt++) {
        cp_wait<1>();
        __syncthreads();
        int ld = kt + 2;
        if (ld < G2_KT) load_stage(ld % 3, ld);
        cp_commit();
        uint32_t stg = sb + (kt % 3) * G2_STAGE;
#pragma unroll
        for (int s = 0; s < 4; s++) {
            uint32_t a[4][4], b[2][4];
#pragma unroll
            for (int mt = 0; mt < 4; mt++)
                ldsm4(a[mt], stg + abase[mt] + (((s * 2 + khalf) ^ axor[mt]) << 4));
#pragma unroll
            for (int nt = 0; nt < 2; nt++)
                ldsm4(b[nt], stg + G2_AB + bbase[nt] + (((s * 2 + khalf) ^ bxor[nt]) << 4));
#pragma unroll
            for (int mt = 0; mt < 4; mt++)
#pragma unroll
                for (int nb = 0; nb < 4; nb++)
                    mma_f16(acc[mt][nb], a[mt], b[nb >> 1][nb & 1], b[nb >> 1][(nb & 1) + 2]);
        }
    }
    cp_wait<0>();

    const int grp = lane >> 2, th2 = (lane & 3) * 2;
#pragma unroll
    for (int mt = 0; mt < 4; mt++) {
        int r0 = m0 + wm + mt * 16 + grp;
#pragma unroll
        for (int nb = 0; nb < 4; nb++) {
            int col = n0 + wn + nb * 8 + th2;
            float2 bv = *(const float2*)(bias + col);
            float2 o0 = make_float2(acc[mt][nb][0] + bv.x, acc[mt][nb][1] + bv.y);
            float2 o1 = make_float2(acc[mt][nb][2] + bv.x, acc[mt][nb][3] + bv.y);
            *(float2*)(out + (size_t)r0 * DMODEL + col) = o0;
            *(float2*)(out + (size_t)(r0 + 8) * DMODEL + col) = o1;
        }
    }
}

// ---------------------------------------------------------------------------
extern "C" void kernel_launch(void* const* d_in, const int* in_sizes, int n_in,
                              void* d_out, int out_size) {
    const float* x  = (const float*)d_in[0];
    const float* Wg = (const float*)d_in[1];
    const float* A  = (const float*)d_in[2];
    const float* B  = (const float*)d_in[3];
    const float* Wb = (const float*)d_in[4];
    const float* bb = (const float*)d_in[5];
    float* out = (float*)d_out;

    static int attr_done = 0;
    if (!attr_done) {
        cudaFuncSetAttribute(g1_kernel, cudaFuncAttributeMaxDynamicSharedMemorySize, G1_SMEM);
        cudaFuncSetAttribute(g2_kernel, cudaFuncAttributeMaxDynamicSharedMemorySize, G2_SMEM);
        attr_done = 1;
    }

    prep_all<<<1664, 256>>>(Wb, B, A);
    gating_cvt<<<N_TOK / 32, 256>>>(x, Wg);
    g1_kernel<<<dim3(2, N_TOK / 64), 128, G1_SMEM>>>();
    g2_kernel<<<dim3(DMODEL / 128, N_TOK / 128), 256, G2_SMEM>>>(bb, out);
}